// round 1
// baseline (speedup 1.0000x reference)
#include <cuda_runtime.h>
#include <math.h>

// Problem constants (fixed by setup_inputs)
#define BB   2
#define SS   2048
#define DD   1024
#define HH   16
#define DHD  64
#define MR   (BB*SS)        // 4096 rows (b*s)
#define NC   (HH*DHD)       // 1024 cols (h*e)
#define WN   (HH*DD*DHD)    // 1048576 weight elems

// ---------------- scratch (static device globals; no allocation) -------------
__device__ unsigned g_amax[6];
__device__ float g_Wq[DD*NC];
__device__ float g_Wk[DD*NC];
__device__ float g_Wv[DD*NC];
__device__ float g_bq[NC], g_bk[NC], g_bv[NC];
__device__ float g_q[(size_t)MR*NC], g_k[(size_t)MR*NC], g_v[(size_t)MR*NC], g_z[(size_t)MR*NC];
__device__ float g_sin[SS*32], g_cos[SS*32];

// ---------------- quant-dequant helpers --------------------------------------
__device__ __forceinline__ float qdq(float w, float amax) {
    float scale = 448.0f / fmaxf(amax, 1e-12f);
    float v = w * scale;
    float a = fabsf(v);
    int ex;
    frexpf(fmaxf(a, 1e-30f), &ex);           // a = m*2^ex, m in [0.5,1) -> floor(log2 a)=ex-1
    float e = fminf(fmaxf((float)(ex - 1), -6.0f), 8.0f);
    float step = exp2f(e - 3.0f);
    float q = rintf(v / step) * step;        // rintf = round-half-even, matches jnp.round
    q = fminf(fmaxf(q, -448.0f), 448.0f);
    return q / scale;
}

__global__ void reset_kernel() {
    if (threadIdx.x < 6) g_amax[threadIdx.x] = 0u;
}

__global__ void amax_kernel(const float* __restrict__ x, int n, int slot) {
    __shared__ float red[256];
    float m = 0.0f;
    for (int i = blockIdx.x * blockDim.x + threadIdx.x; i < n; i += gridDim.x * blockDim.x)
        m = fmaxf(m, fabsf(x[i]));
    red[threadIdx.x] = m;
    __syncthreads();
    for (int s = 128; s > 0; s >>= 1) {
        if (threadIdx.x < s) red[threadIdx.x] = fmaxf(red[threadIdx.x], red[threadIdx.x + s]);
        __syncthreads();
    }
    if (threadIdx.x == 0) atomicMax(&g_amax[slot], __float_as_uint(red[0]));
}

// quantize + transpose W[h,d,e] -> Wt[d, h*64+e]
__global__ void quant_w_kernel(const float* __restrict__ W, float* __restrict__ Wt, int slot) {
    int idx = blockIdx.x * 256 + threadIdx.x;
    if (idx >= WN) return;
    float amax = __uint_as_float(g_amax[slot]);
    int h   = idx / (DD * DHD);
    int rem = idx % (DD * DHD);
    int d = rem / DHD, e = rem % DHD;
    Wt[(size_t)d * NC + h * DHD + e] = qdq(W[idx], amax);
}

__global__ void quant_b_kernel(const float* __restrict__ b, float* __restrict__ bt, int slot) {
    int idx = blockIdx.x * 256 + threadIdx.x;
    if (idx >= NC) return;
    float amax = __uint_as_float(g_amax[slot]);
    bt[idx] = qdq(b[idx], amax);
}

// ---------------- rotary table + apply ---------------------------------------
__global__ void sincos_kernel() {
    int idx = blockIdx.x * 256 + threadIdx.x;
    if (idx >= SS * 32) return;
    int pos = idx >> 5, i = idx & 31;
    float invf = (float)pow(10000.0, -(double)i / 32.0);   // fp32-rounded inv_freq (matches ref)
    float ang  = (float)pos * invf;                        // fp32-rounded angle (matches ref)
    g_sin[idx] = (float)sin((double)ang);
    g_cos[idx] = (float)cos((double)ang);
}

// x[..0:32],x[..32:64] rotated pairwise; outscale folds the 1/sqrt(Dh) into q
__global__ void rotary_kernel(float* __restrict__ buf, float outscale) {
    int idx = blockIdx.x * 256 + threadIdx.x;              // MR*HH*32 = 2097152
    if (idx >= MR * HH * 32) return;
    int bs  = idx / (HH * 32);
    int rem = idx % (HH * 32);
    int h = rem >> 5, i = rem & 31;
    int pos = bs & (SS - 1);
    size_t base = (size_t)bs * NC + h * DHD;
    float x0 = buf[base + i], x1 = buf[base + i + 32];
    float c = g_cos[pos * 32 + i], s = g_sin[pos * 32 + i];
    buf[base + i]      = (x0 * c - x1 * s) * outscale;
    buf[base + i + 32] = (x1 * c + x0 * s) * outscale;
}

// ---------------- SGEMM 128x128x8, 256 threads, 8x8 per thread ---------------
// C[M,N] = A[M,K] * B[K,N] + bias[N]     (M%128==0, N%128==0, K%8==0)
__global__ void __launch_bounds__(256) sgemm_kernel(
        const float* __restrict__ A, const float* __restrict__ B,
        const float* __restrict__ bias, float* __restrict__ C,
        int M, int N, int K) {
    __shared__ float As[8][128];
    __shared__ float Bs[8][128];
    int tid = threadIdx.x;
    int bm = blockIdx.y, bn = blockIdx.x;
    int tx = tid & 15, ty = tid >> 4;
    int arow = tid >> 1;
    int acol = (tid & 1) * 4;
    int brow = tid >> 5;
    int bcol = (tid & 31) * 4;
    float acc[8][8];
#pragma unroll
    for (int i = 0; i < 8; i++)
#pragma unroll
        for (int j = 0; j < 8; j++) acc[i][j] = 0.0f;

    const float* Ab = A + (size_t)(bm * 128) * K;
    const float* Bb = B + bn * 128;

    for (int k0 = 0; k0 < K; k0 += 8) {
        float4 av = *(const float4*)(Ab + (size_t)arow * K + k0 + acol);
        float4 bv = *(const float4*)(Bb + (size_t)(k0 + brow) * N + bcol);
        As[acol + 0][arow] = av.x;
        As[acol + 1][arow] = av.y;
        As[acol + 2][arow] = av.z;
        As[acol + 3][arow] = av.w;
        *(float4*)&Bs[brow][bcol] = bv;
        __syncthreads();
#pragma unroll
        for (int kk = 0; kk < 8; kk++) {
            float a[8], b8[8];
            *(float4*)&a[0]  = *(const float4*)&As[kk][ty * 8];
            *(float4*)&a[4]  = *(const float4*)&As[kk][ty * 8 + 4];
            *(float4*)&b8[0] = *(const float4*)&Bs[kk][tx * 8];
            *(float4*)&b8[4] = *(const float4*)&Bs[kk][tx * 8 + 4];
#pragma unroll
            for (int i = 0; i < 8; i++)
#pragma unroll
                for (int j = 0; j < 8; j++) acc[i][j] += a[i] * b8[j];
        }
        __syncthreads();
    }
    int crow0 = bm * 128 + ty * 8;
    int ccol0 = bn * 128 + tx * 8;
#pragma unroll
    for (int i = 0; i < 8; i++) {
        size_t roff = (size_t)(crow0 + i) * N + ccol0;
#pragma unroll
        for (int j = 0; j < 8; j++)
            C[roff + j] = acc[i][j] + bias[ccol0 + j];
    }
}

// ---------------- flash attention, fp32, BM=BN=64, Dh=64 ---------------------
#define PADW 68
__global__ void __launch_bounds__(256) attn_kernel(
        const float* __restrict__ Q, const float* __restrict__ K,
        const float* __restrict__ V, float* __restrict__ Z) {
    extern __shared__ float sm[];
    float* Qs = sm;                    // [64][PADW]  Qs[e][q]
    float* Ks = Qs + 64 * PADW;        // [64][PADW]  Ks[e][k]
    float* Vs = Ks + 64 * PADW;        // [64][PADW]  Vs[k][d]
    float* Ps = Vs + 64 * PADW;        // [64][PADW]  Ps[q][k]

    int qt = blockIdx.x, h = blockIdx.y, b = blockIdx.z;
    int tid = threadIdx.x;
    int tx = tid & 15, ty = tid >> 4;
    int q0 = qt * 64;

    const float* Qb = Q + ((size_t)b * SS + q0) * NC + h * DHD;
    for (int t = tid; t < 64 * 64; t += 256) {
        int r = t >> 6, e = t & 63;
        Qs[e * PADW + r] = Qb[(size_t)r * NC + e];
    }

    float m_i[4], l_i[4], acc[4][4];
#pragma unroll
    for (int i = 0; i < 4; i++) {
        m_i[i] = -INFINITY;
        l_i[i] = 0.0f;
#pragma unroll
        for (int j = 0; j < 4; j++) acc[i][j] = 0.0f;
    }
    __syncthreads();

    int nk = (qt + 1) * 64;
    for (int k0 = 0; k0 < nk; k0 += 64) {
        const float* Kb = K + ((size_t)b * SS + k0) * NC + h * DHD;
        const float* Vb = V + ((size_t)b * SS + k0) * NC + h * DHD;
        for (int t = tid; t < 64 * 64; t += 256) {
            int r = t >> 6, e = t & 63;
            Ks[e * PADW + r] = Kb[(size_t)r * NC + e];
            Vs[r * PADW + e] = Vb[(size_t)r * NC + e];
        }
        __syncthreads();

        float s[4][4];
#pragma unroll
        for (int i = 0; i < 4; i++)
#pragma unroll
            for (int j = 0; j < 4; j++) s[i][j] = 0.0f;

        for (int kk = 0; kk < 64; kk++) {
            float qv[4], kv[4];
            *(float4*)qv = *(const float4*)&Qs[kk * PADW + ty * 4];
            *(float4*)kv = *(const float4*)&Ks[kk * PADW + tx * 4];
#pragma unroll
            for (int i = 0; i < 4; i++)
#pragma unroll
                for (int j = 0; j < 4; j++) s[i][j] += qv[i] * kv[j];
        }

        bool diag = (k0 + 63 > q0);   // only diagonal tile needs masking
        if (diag) {
#pragma unroll
            for (int i = 0; i < 4; i++) {
                int qg = q0 + ty * 4 + i;
#pragma unroll
                for (int j = 0; j < 4; j++) {
                    int kg = k0 + tx * 4 + j;
                    if (kg > qg) s[i][j] = -1000.0f;
                }
            }
        }

#pragma unroll
        for (int i = 0; i < 4; i++) {
            float rm = fmaxf(fmaxf(s[i][0], s[i][1]), fmaxf(s[i][2], s[i][3]));
#pragma unroll
            for (int off = 8; off >= 1; off >>= 1)
                rm = fmaxf(rm, __shfl_xor_sync(0xffffffffu, rm, off));
            float mnew = fmaxf(m_i[i], rm);
            float corr = expf(m_i[i] - mnew);
            float rs = 0.0f;
#pragma unroll
            for (int j = 0; j < 4; j++) {
                float p = expf(s[i][j] - mnew);
                s[i][j] = p;
                rs += p;
            }
#pragma unroll
            for (int off = 8; off >= 1; off >>= 1)
                rs += __shfl_xor_sync(0xffffffffu, rs, off);
            l_i[i] = l_i[i] * corr + rs;
            m_i[i] = mnew;
#pragma unroll
            for (int j = 0; j < 4; j++) acc[i][j] *= corr;
        }

#pragma unroll
        for (int i = 0; i < 4; i++)
#pragma unroll
            for (int j = 0; j < 4; j++)
                Ps[(ty * 4 + i) * PADW + tx * 4 + j] = s[i][j];
        __syncthreads();

        for (int kk = 0; kk < 64; kk++) {
            float vv[4];
            *(float4*)vv = *(const float4*)&Vs[kk * PADW + tx * 4];
            float pv[4];
#pragma unroll
            for (int i = 0; i < 4; i++) pv[i] = Ps[(ty * 4 + i) * PADW + kk];
#pragma unroll
            for (int i = 0; i < 4; i++)
#pragma unroll
                for (int j = 0; j < 4; j++) acc[i][j] += pv[i] * vv[j];
        }
        __syncthreads();
    }

    float* Zb = Z + ((size_t)b * SS + q0) * NC + h * DHD;
#pragma unroll
    for (int i = 0; i < 4; i++) {
        float inv = 1.0f / l_i[i];
#pragma unroll
        for (int j = 0; j < 4; j++)
            Zb[(size_t)(ty * 4 + i) * NC + tx * 4 + j] = acc[i][j] * inv;
    }
}

// ---------------- launch ------------------------------------------------------
extern "C" void kernel_launch(void* const* d_in, const int* in_sizes, int n_in,
                              void* d_out, int out_size) {
    const float* Xq  = (const float*)d_in[0];
    const float* Xk  = (const float*)d_in[1];
    const float* Xv  = (const float*)d_in[2];
    const float* WQ  = (const float*)d_in[3];
    const float* WK  = (const float*)d_in[4];
    const float* WV  = (const float*)d_in[5];
    const float* WO  = (const float*)d_in[6];
    const float* bQ  = (const float*)d_in[7];
    const float* bK  = (const float*)d_in[8];
    const float* bV  = (const float*)d_in[9];
    const float* bO  = (const float*)d_in[10];
    float* out = (float*)d_out;

    static float *pWq=nullptr,*pWk=nullptr,*pWv=nullptr,*pbq=nullptr,*pbk=nullptr,*pbv=nullptr;
    static float *pq=nullptr,*pk=nullptr,*pv=nullptr,*pz=nullptr;
    if (!pWq) {
        cudaGetSymbolAddress((void**)&pWq, g_Wq);
        cudaGetSymbolAddress((void**)&pWk, g_Wk);
        cudaGetSymbolAddress((void**)&pWv, g_Wv);
        cudaGetSymbolAddress((void**)&pbq, g_bq);
        cudaGetSymbolAddress((void**)&pbk, g_bk);
        cudaGetSymbolAddress((void**)&pbv, g_bv);
        cudaGetSymbolAddress((void**)&pq,  g_q);
        cudaGetSymbolAddress((void**)&pk,  g_k);
        cudaGetSymbolAddress((void**)&pv,  g_v);
        cudaGetSymbolAddress((void**)&pz,  g_z);
    }
    cudaFuncSetAttribute(attn_kernel, cudaFuncAttributeMaxDynamicSharedMemorySize,
                         4 * 64 * PADW * (int)sizeof(float));

    // 1) quant-dequant weights/biases (+ transpose into GEMM layout)
    reset_kernel<<<1, 32>>>();
    amax_kernel<<<256, 256>>>(WQ, WN, 0);
    amax_kernel<<<256, 256>>>(WK, WN, 1);
    amax_kernel<<<256, 256>>>(WV, WN, 2);
    amax_kernel<<<4, 256>>>(bQ, NC, 3);
    amax_kernel<<<4, 256>>>(bK, NC, 4);
    amax_kernel<<<4, 256>>>(bV, NC, 5);
    quant_w_kernel<<<WN / 256, 256>>>(WQ, pWq, 0);
    quant_w_kernel<<<WN / 256, 256>>>(WK, pWk, 1);
    quant_w_kernel<<<WN / 256, 256>>>(WV, pWv, 2);
    quant_b_kernel<<<4, 256>>>(bQ, pbq, 3);
    quant_b_kernel<<<4, 256>>>(bK, pbk, 4);
    quant_b_kernel<<<4, 256>>>(bV, pbv, 5);

    // 2) rotary table
    sincos_kernel<<<SS * 32 / 256, 256>>>();

    // 3) projections
    dim3 gg(NC / 128, MR / 128);
    sgemm_kernel<<<gg, 256>>>(Xq, pWq, pbq, pq, MR, NC, DD);
    sgemm_kernel<<<gg, 256>>>(Xk, pWk, pbk, pk, MR, NC, DD);
    sgemm_kernel<<<gg, 256>>>(Xv, pWv, pbv, pv, MR, NC, DD);

    // 4) rotary (q gets the 1/sqrt(Dh)=0.125 attention scale folded in)
    int rot_grid = (MR * HH * 32) / 256;
    rotary_kernel<<<rot_grid, 256>>>(pq, 0.125f);
    rotary_kernel<<<rot_grid, 256>>>(pk, 1.0f);

    // 5) causal flash attention
    dim3 ag(SS / 64, HH, BB);
    attn_kernel<<<ag, 256, 4 * 64 * PADW * (int)sizeof(float)>>>(pq, pk, pv, pz);

    // 6) output projection
    sgemm_kernel<<<gg, 256>>>(pz, WO, bO, out, MR, DD, NC);
}

// round 3
// speedup vs baseline: 1.5225x; 1.5225x over previous
#include <cuda_runtime.h>
#include <cuda_bf16.h>
#include <math.h>
#include <stdint.h>

// Problem constants
#define BB   2
#define SS   2048
#define DD   1024
#define HH   16
#define DHD  64
#define MR   (BB*SS)        // 4096
#define NC   (HH*DHD)       // 1024
#define WN   (HH*DD*DHD)    // 1048576

// ---------------------------------------------------------------- helpers
__device__ __forceinline__ uint32_t smem_u32(const void* p) {
    uint32_t a;
    asm("{ .reg .u64 t; cvta.to.shared.u64 t, %1; cvt.u32.u64 %0, t; }" : "=r"(a) : "l"(p));
    return a;
}

#define CP_ASYNC16(dst, src) asm volatile("cp.async.cg.shared.global [%0], [%1], 16;" :: "r"(dst), "l"(src))
#define CP_COMMIT()  asm volatile("cp.async.commit_group;" ::: "memory")
#define CP_WAIT1()   asm volatile("cp.async.wait_group 1;" ::: "memory")
#define CP_WAIT0()   asm volatile("cp.async.wait_group 0;" ::: "memory")

#define LDSM_X4(r0, r1, r2, r3, addr) \
    asm volatile("ldmatrix.sync.aligned.m8n8.x4.shared.b16 {%0,%1,%2,%3}, [%4];" \
                 : "=r"(r0), "=r"(r1), "=r"(r2), "=r"(r3) : "r"(addr))

#define MMA_BF16(c, a, b0, b1) \
    asm volatile("mma.sync.aligned.m16n8k16.row.col.f32.bf16.bf16.f32 " \
                 "{%0,%1,%2,%3}, {%4,%5,%6,%7}, {%8,%9}, {%0,%1,%2,%3};" \
                 : "+f"((c)[0]), "+f"((c)[1]), "+f"((c)[2]), "+f"((c)[3]) \
                 : "r"((a)[0]), "r"((a)[1]), "r"((a)[2]), "r"((a)[3]), "r"(b0), "r"(b1))

// ---------------------------------------------------------------- scratch
__device__ unsigned g_amax[6];
__device__ __nv_bfloat16 g_Wqh[DD*NC], g_Wql[DD*NC];
__device__ __nv_bfloat16 g_Wkh[DD*NC], g_Wkl[DD*NC];
__device__ __nv_bfloat16 g_Wvh[DD*NC], g_Wvl[DD*NC];
__device__ __nv_bfloat16 g_Woh[NC*DD], g_Wol[NC*DD];
__device__ __nv_bfloat16 g_Xqh[(size_t)MR*DD], g_Xql[(size_t)MR*DD];
__device__ __nv_bfloat16 g_Xkh[(size_t)MR*DD], g_Xkl[(size_t)MR*DD];
__device__ __nv_bfloat16 g_Xvh[(size_t)MR*DD], g_Xvl[(size_t)MR*DD];
__device__ __nv_bfloat16 g_zh[(size_t)MR*NC],  g_zl[(size_t)MR*NC];
__device__ float g_bq[NC], g_bk[NC], g_bv[NC];
__device__ float g_q[(size_t)MR*NC], g_k[(size_t)MR*NC], g_v[(size_t)MR*NC], g_z[(size_t)MR*NC];
__device__ float g_sin[SS*32], g_cos[SS*32];

// ---------------------------------------------------------------- qdq
__device__ __forceinline__ float qdq(float w, float amax) {
    float scale = 448.0f / fmaxf(amax, 1e-12f);
    float v = w * scale;
    float a = fabsf(v);
    int ex;
    frexpf(fmaxf(a, 1e-30f), &ex);
    float e = fminf(fmaxf((float)(ex - 1), -6.0f), 8.0f);
    float step = exp2f(e - 3.0f);
    float q = rintf(v / step) * step;
    q = fminf(fmaxf(q, -448.0f), 448.0f);
    return q / scale;
}

__global__ void reset_kernel() {
    if (threadIdx.x < 6) g_amax[threadIdx.x] = 0u;
}

__global__ void amax_kernel(const float4* __restrict__ x, int n4, int slot) {
    __shared__ float red[256];
    float m = 0.0f;
    for (int i = blockIdx.x * blockDim.x + threadIdx.x; i < n4; i += gridDim.x * blockDim.x) {
        float4 v = x[i];
        m = fmaxf(m, fmaxf(fmaxf(fabsf(v.x), fabsf(v.y)), fmaxf(fabsf(v.z), fabsf(v.w))));
    }
    red[threadIdx.x] = m;
    __syncthreads();
    for (int s = 128; s > 0; s >>= 1) {
        if (threadIdx.x < s) red[threadIdx.x] = fmaxf(red[threadIdx.x], red[threadIdx.x + s]);
        __syncthreads();
    }
    if (threadIdx.x == 0) atomicMax(&g_amax[slot], __float_as_uint(red[0]));
}

__device__ __forceinline__ void split_bf16(float x, __nv_bfloat16& h, __nv_bfloat16& l) {
    h = __float2bfloat16(x);
    l = __float2bfloat16(x - __bfloat162float(h));
}

// qdq + transpose W[h,d,e] -> B[n=h*64+e][k=d], split into hi/lo bf16
__global__ void quant_w_t_kernel(const float* __restrict__ W,
                                 __nv_bfloat16* __restrict__ Bh, __nv_bfloat16* __restrict__ Bl,
                                 int slot) {
    __shared__ float t[32][33];
    float amax = __uint_as_float(g_amax[slot]);
    int h = blockIdx.z;
    int d = blockIdx.x * 32 + threadIdx.y;
    int e = blockIdx.y * 32 + threadIdx.x;
    t[threadIdx.y][threadIdx.x] = qdq(W[(size_t)h * DD * DHD + d * DHD + e], amax);
    __syncthreads();
    int n = h * DHD + blockIdx.y * 32 + threadIdx.y;
    int k = blockIdx.x * 32 + threadIdx.x;
    __nv_bfloat16 hi, lo;
    split_bf16(t[threadIdx.x][threadIdx.y], hi, lo);
    Bh[(size_t)n * DD + k] = hi;
    Bl[(size_t)n * DD + k] = lo;
}

// transpose WO[he][d] -> B[n=d][k=he], split (no qdq)
__global__ void wo_t_kernel(const float* __restrict__ W,
                            __nv_bfloat16* __restrict__ Bh, __nv_bfloat16* __restrict__ Bl) {
    __shared__ float t[32][33];
    int he = blockIdx.y * 32 + threadIdx.y;
    int d  = blockIdx.x * 32 + threadIdx.x;
    t[threadIdx.y][threadIdx.x] = W[(size_t)he * DD + d];
    __syncthreads();
    int n = blockIdx.x * 32 + threadIdx.y;   // d
    int k = blockIdx.y * 32 + threadIdx.x;   // he
    __nv_bfloat16 hi, lo;
    split_bf16(t[threadIdx.x][threadIdx.y], hi, lo);
    Bh[(size_t)n * NC + k] = hi;
    Bl[(size_t)n * NC + k] = lo;
}

__global__ void quant_b_kernel(const float* __restrict__ b, float* __restrict__ bt, int slot) {
    int idx = blockIdx.x * 256 + threadIdx.x;
    if (idx >= NC) return;
    float amax = __uint_as_float(g_amax[slot]);
    bt[idx] = qdq(b[idx], amax);
}

// fp32 -> bf16 hi/lo split (vectorized)
__global__ void split_kernel(const float4* __restrict__ x,
                             __nv_bfloat162* __restrict__ hi, __nv_bfloat162* __restrict__ lo,
                             int n4) {
    int i = blockIdx.x * 256 + threadIdx.x;
    if (i >= n4) return;
    float4 v = x[i];
    __nv_bfloat16 h0, h1, h2, h3, l0, l1, l2, l3;
    split_bf16(v.x, h0, l0);
    split_bf16(v.y, h1, l1);
    split_bf16(v.z, h2, l2);
    split_bf16(v.w, h3, l3);
    hi[2*i]   = __nv_bfloat162(h0, h1);
    hi[2*i+1] = __nv_bfloat162(h2, h3);
    lo[2*i]   = __nv_bfloat162(l0, l1);
    lo[2*i+1] = __nv_bfloat162(l2, l3);
}

// ---------------------------------------------------------------- rotary
__global__ void sincos_kernel() {
    int idx = blockIdx.x * 256 + threadIdx.x;
    if (idx >= SS * 32) return;
    int pos = idx >> 5, i = idx & 31;
    float invf = (float)pow(10000.0, -(double)i / 32.0);
    float ang  = (float)pos * invf;
    g_sin[idx] = (float)sin((double)ang);
    g_cos[idx] = (float)cos((double)ang);
}

__global__ void rotary_kernel(float* __restrict__ buf, float outscale) {
    int idx = blockIdx.x * 256 + threadIdx.x;
    if (idx >= MR * HH * 32) return;
    int bs  = idx / (HH * 32);
    int rem = idx % (HH * 32);
    int h = rem >> 5, i = rem & 31;
    int pos = bs & (SS - 1);
    size_t base = (size_t)bs * NC + h * DHD;
    float x0 = buf[base + i], x1 = buf[base + i + 32];
    float c = g_cos[pos * 32 + i], s = g_sin[pos * 32 + i];
    buf[base + i]      = (x0 * c - x1 * s) * outscale;
    buf[base + i + 32] = (x1 * c + x0 * s) * outscale;
}

// ---------------------------------------------------------------- HMMA GEMM
// C[M,N] = (Ah+Al)[M,K] * (Bh+Bl)[N,K]^T + bias[N]   (split-bf16, 3 passes)
// Tile 128x128, KC=32, double-buffered cp.async, mma.sync m16n8k16 bf16.
#define KC 32
#define PK 40                       // padded k stride (bf16) -> 80B rows, LDSM conflict-free
#define TILE_B (128 * PK * 2)       // 10240 bytes per operand tile
#define STAGE_B (4 * TILE_B)        // Ah, Al, Bh, Bl
#define GEMM_SMEM (2 * STAGE_B)     // 81920

__global__ void __launch_bounds__(256) tgemm_kernel(
        const __nv_bfloat16* __restrict__ Ah, const __nv_bfloat16* __restrict__ Al,
        const __nv_bfloat16* __restrict__ Bh, const __nv_bfloat16* __restrict__ Bl,
        const float* __restrict__ bias, float* __restrict__ C,
        int M, int N, int K) {
    extern __shared__ char sm[];
    uint32_t sb = smem_u32(sm);
    int tid = threadIdx.x;
    int lane = tid & 31, wid = tid >> 5;
    int wm = wid & 3, wn = wid >> 2;
    int bm = blockIdx.y, bn = blockIdx.x;

    const char* srcs[4] = {
        (const char*)(Ah + (size_t)bm * 128 * K),
        (const char*)(Al + (size_t)bm * 128 * K),
        (const char*)(Bh + (size_t)bn * 128 * K),
        (const char*)(Bl + (size_t)bn * 128 * K) };

    auto fill = [&](int s, int kc) {
        uint32_t base = sb + s * STAGE_B;
        size_t koff = (size_t)kc * KC * 2;
#pragma unroll
        for (int t = tid; t < 2048; t += 256) {
            int arr = t >> 9;
            int idx = t & 511;
            int row = idx >> 2, c = idx & 3;
            CP_ASYNC16(base + arr * TILE_B + row * (PK * 2) + c * 16,
                       srcs[arr] + (size_t)row * K * 2 + koff + c * 16);
        }
        CP_COMMIT();
    };

    float acc[2][8][4];
#pragma unroll
    for (int i = 0; i < 2; i++)
#pragma unroll
        for (int j = 0; j < 8; j++)
#pragma unroll
            for (int r = 0; r < 4; r++) acc[i][j][r] = 0.0f;

    // ldmatrix lane address components
    int a_row = (lane & 7) + ((lane >> 3) & 1) * 8;   // row within 16
    int a_k   = (lane >> 4) * 8;                       // k-half
    int b_n   = ((lane >> 4) * 8) + (lane & 7);        // n within 16
    int b_k   = ((lane >> 3) & 1) * 8;                 // k-half

    int nk = K / KC;
    fill(0, 0);
    fill(1, 1);

    for (int c = 0; c < nk; c++) {
        int s = c & 1;
        if (c + 1 < nk) CP_WAIT1(); else CP_WAIT0();
        __syncthreads();

        uint32_t stb = sb + s * STAGE_B;
        uint32_t As_h = stb;
        uint32_t As_l = stb + TILE_B;
        uint32_t Bs_h = stb + 2 * TILE_B;
        uint32_t Bs_l = stb + 3 * TILE_B;

#pragma unroll
        for (int kk = 0; kk < 2; kk++) {
            uint32_t ah[2][4], al[2][4];
#pragma unroll
            for (int i = 0; i < 2; i++) {
                uint32_t off = ((wm * 32 + i * 16 + a_row) * PK + kk * 16 + a_k) * 2;
                LDSM_X4(ah[i][0], ah[i][1], ah[i][2], ah[i][3], As_h + off);
                LDSM_X4(al[i][0], al[i][1], al[i][2], al[i][3], As_l + off);
            }
#pragma unroll
            for (int jj = 0; jj < 4; jj++) {
                uint32_t boff = ((wn * 64 + jj * 16 + b_n) * PK + kk * 16 + b_k) * 2;
                uint32_t bh[4], bl[4];
                LDSM_X4(bh[0], bh[1], bh[2], bh[3], Bs_h + boff);
                LDSM_X4(bl[0], bl[1], bl[2], bl[3], Bs_l + boff);
#pragma unroll
                for (int i = 0; i < 2; i++) {
                    MMA_BF16(acc[i][2 * jj],     ah[i], bh[0], bh[1]);
                    MMA_BF16(acc[i][2 * jj + 1], ah[i], bh[2], bh[3]);
                    MMA_BF16(acc[i][2 * jj],     ah[i], bl[0], bl[1]);
                    MMA_BF16(acc[i][2 * jj + 1], ah[i], bl[2], bl[3]);
                    MMA_BF16(acc[i][2 * jj],     al[i], bh[0], bh[1]);
                    MMA_BF16(acc[i][2 * jj + 1], al[i], bh[2], bh[3]);
                }
            }
        }
        __syncthreads();
        if (c + 2 < nk) fill(s, c + 2);
    }

    // epilogue
#pragma unroll
    for (int i = 0; i < 2; i++) {
        int r0 = bm * 128 + wm * 32 + i * 16 + (lane >> 2);
#pragma unroll
        for (int j = 0; j < 8; j++) {
            int c0 = bn * 128 + wn * 64 + j * 8 + (lane & 3) * 2;
            float bx = bias[c0], by = bias[c0 + 1];
            float2 v0 = make_float2(acc[i][j][0] + bx, acc[i][j][1] + by);
            float2 v1 = make_float2(acc[i][j][2] + bx, acc[i][j][3] + by);
            *(float2*)&C[(size_t)r0 * N + c0] = v0;
            *(float2*)&C[(size_t)(r0 + 8) * N + c0] = v1;
        }
    }
}

// ---------------------------------------------------------------- flash attention fp32
#define PADW 68
__global__ void __launch_bounds__(256) attn_kernel(
        const float* __restrict__ Q, const float* __restrict__ K,
        const float* __restrict__ V, float* __restrict__ Z) {
    extern __shared__ float smf[];
    float* Qs = smf;
    float* Ks = Qs + 64 * PADW;
    float* Vs = Ks + 64 * PADW;
    float* Ps = Vs + 64 * PADW;

    int qt = blockIdx.x, h = blockIdx.y, b = blockIdx.z;
    int tid = threadIdx.x;
    int tx = tid & 15, ty = tid >> 4;
    int q0 = qt * 64;

    const float* Qb = Q + ((size_t)b * SS + q0) * NC + h * DHD;
    for (int t = tid; t < 64 * 64; t += 256) {
        int r = t >> 6, e = t & 63;
        Qs[e * PADW + r] = Qb[(size_t)r * NC + e];
    }

    float m_i[4], l_i[4], acc[4][4];
#pragma unroll
    for (int i = 0; i < 4; i++) {
        m_i[i] = -INFINITY;
        l_i[i] = 0.0f;
#pragma unroll
        for (int j = 0; j < 4; j++) acc[i][j] = 0.0f;
    }
    __syncthreads();

    int nk = (qt + 1) * 64;
    for (int k0 = 0; k0 < nk; k0 += 64) {
        const float* Kb = K + ((size_t)b * SS + k0) * NC + h * DHD;
        const float* Vb = V + ((size_t)b * SS + k0) * NC + h * DHD;
        for (int t = tid; t < 64 * 64; t += 256) {
            int r = t >> 6, e = t & 63;
            Ks[e * PADW + r] = Kb[(size_t)r * NC + e];
            Vs[r * PADW + e] = Vb[(size_t)r * NC + e];
        }
        __syncthreads();

        float s[4][4];
#pragma unroll
        for (int i = 0; i < 4; i++)
#pragma unroll
            for (int j = 0; j < 4; j++) s[i][j] = 0.0f;

        for (int kk = 0; kk < 64; kk++) {
            float qv[4], kv[4];
            *(float4*)qv = *(const float4*)&Qs[kk * PADW + ty * 4];
            *(float4*)kv = *(const float4*)&Ks[kk * PADW + tx * 4];
#pragma unroll
            for (int i = 0; i < 4; i++)
#pragma unroll
                for (int j = 0; j < 4; j++) s[i][j] += qv[i] * kv[j];
        }

        bool diag = (k0 + 63 > q0);
        if (diag) {
#pragma unroll
            for (int i = 0; i < 4; i++) {
                int qg = q0 + ty * 4 + i;
#pragma unroll
                for (int j = 0; j < 4; j++) {
                    int kg = k0 + tx * 4 + j;
                    if (kg > qg) s[i][j] = -1000.0f;
                }
            }
        }

#pragma unroll
        for (int i = 0; i < 4; i++) {
            float rm = fmaxf(fmaxf(s[i][0], s[i][1]), fmaxf(s[i][2], s[i][3]));
#pragma unroll
            for (int off = 8; off >= 1; off >>= 1)
                rm = fmaxf(rm, __shfl_xor_sync(0xffffffffu, rm, off));
            float mnew = fmaxf(m_i[i], rm);
            float corr = expf(m_i[i] - mnew);
            float rs = 0.0f;
#pragma unroll
            for (int j = 0; j < 4; j++) {
                float p = expf(s[i][j] - mnew);
                s[i][j] = p;
                rs += p;
            }
#pragma unroll
            for (int off = 8; off >= 1; off >>= 1)
                rs += __shfl_xor_sync(0xffffffffu, rs, off);
            l_i[i] = l_i[i] * corr + rs;
            m_i[i] = mnew;
#pragma unroll
            for (int j = 0; j < 4; j++) acc[i][j] *= corr;
        }

#pragma unroll
        for (int i = 0; i < 4; i++)
#pragma unroll
            for (int j = 0; j < 4; j++)
                Ps[(ty * 4 + i) * PADW + tx * 4 + j] = s[i][j];
        __syncthreads();

        for (int kk = 0; kk < 64; kk++) {
            float vv[4];
            *(float4*)vv = *(const float4*)&Vs[kk * PADW + tx * 4];
            float pv[4];
#pragma unroll
            for (int i = 0; i < 4; i++) pv[i] = Ps[(ty * 4 + i) * PADW + kk];
#pragma unroll
            for (int i = 0; i < 4; i++)
#pragma unroll
                for (int j = 0; j < 4; j++) acc[i][j] += pv[i] * vv[j];
        }
        __syncthreads();
    }

    float* Zb = Z + ((size_t)b * SS + q0) * NC + h * DHD;
#pragma unroll
    for (int i = 0; i < 4; i++) {
        float inv = 1.0f / l_i[i];
#pragma unroll
        for (int j = 0; j < 4; j++)
            Zb[(size_t)(ty * 4 + i) * NC + tx * 4 + j] = acc[i][j] * inv;
    }
}

// ---------------------------------------------------------------- launch
extern "C" void kernel_launch(void* const* d_in, const int* in_sizes, int n_in,
                              void* d_out, int out_size) {
    const float* Xq  = (const float*)d_in[0];
    const float* Xk  = (const float*)d_in[1];
    const float* Xv  = (const float*)d_in[2];
    const float* WQ  = (const float*)d_in[3];
    const float* WK  = (const float*)d_in[4];
    const float* WV  = (const float*)d_in[5];
    const float* WO  = (const float*)d_in[6];
    const float* bQ  = (const float*)d_in[7];
    const float* bK  = (const float*)d_in[8];
    const float* bV  = (const float*)d_in[9];
    const float* bO  = (const float*)d_in[10];
    float* out = (float*)d_out;

    static bool init = false;
    static __nv_bfloat16 *pWqh, *pWql, *pWkh, *pWkl, *pWvh, *pWvl, *pWoh, *pWol;
    static __nv_bfloat16 *pXqh, *pXql, *pXkh, *pXkl, *pXvh, *pXvl, *pzh, *pzl;
    static float *pbq, *pbk, *pbv, *pq, *pk, *pv, *pz;
    if (!init) {
        cudaGetSymbolAddress((void**)&pWqh, g_Wqh); cudaGetSymbolAddress((void**)&pWql, g_Wql);
        cudaGetSymbolAddress((void**)&pWkh, g_Wkh); cudaGetSymbolAddress((void**)&pWkl, g_Wkl);
        cudaGetSymbolAddress((void**)&pWvh, g_Wvh); cudaGetSymbolAddress((void**)&pWvl, g_Wvl);
        cudaGetSymbolAddress((void**)&pWoh, g_Woh); cudaGetSymbolAddress((void**)&pWol, g_Wol);
        cudaGetSymbolAddress((void**)&pXqh, g_Xqh); cudaGetSymbolAddress((void**)&pXql, g_Xql);
        cudaGetSymbolAddress((void**)&pXkh, g_Xkh); cudaGetSymbolAddress((void**)&pXkl, g_Xkl);
        cudaGetSymbolAddress((void**)&pXvh, g_Xvh); cudaGetSymbolAddress((void**)&pXvl, g_Xvl);
        cudaGetSymbolAddress((void**)&pzh,  g_zh);  cudaGetSymbolAddress((void**)&pzl,  g_zl);
        cudaGetSymbolAddress((void**)&pbq, g_bq); cudaGetSymbolAddress((void**)&pbk, g_bk);
        cudaGetSymbolAddress((void**)&pbv, g_bv);
        cudaGetSymbolAddress((void**)&pq, g_q); cudaGetSymbolAddress((void**)&pk, g_k);
        cudaGetSymbolAddress((void**)&pv, g_v); cudaGetSymbolAddress((void**)&pz, g_z);
        cudaFuncSetAttribute(attn_kernel, cudaFuncAttributeMaxDynamicSharedMemorySize,
                             4 * 64 * PADW * (int)sizeof(float));
        cudaFuncSetAttribute(tgemm_kernel, cudaFuncAttributeMaxDynamicSharedMemorySize, GEMM_SMEM);
        init = true;
    }

    // 1) amax reductions
    reset_kernel<<<1, 32>>>();
    amax_kernel<<<512, 256>>>((const float4*)WQ, WN / 4, 0);
    amax_kernel<<<512, 256>>>((const float4*)WK, WN / 4, 1);
    amax_kernel<<<512, 256>>>((const float4*)WV, WN / 4, 2);
    amax_kernel<<<2, 256>>>((const float4*)bQ, NC / 4, 3);
    amax_kernel<<<2, 256>>>((const float4*)bK, NC / 4, 4);
    amax_kernel<<<2, 256>>>((const float4*)bV, NC / 4, 5);

    // 2) weight qdq + transpose + split to bf16 hi/lo
    dim3 wt_grid(DD / 32, DHD / 32, HH);
    dim3 wt_blk(32, 32);
    quant_w_t_kernel<<<wt_grid, wt_blk>>>(WQ, pWqh, pWql, 0);
    quant_w_t_kernel<<<wt_grid, wt_blk>>>(WK, pWkh, pWkl, 1);
    quant_w_t_kernel<<<wt_grid, wt_blk>>>(WV, pWvh, pWvl, 2);
    wo_t_kernel<<<dim3(DD / 32, NC / 32), wt_blk>>>(WO, pWoh, pWol);
    quant_b_kernel<<<4, 256>>>(bQ, pbq, 3);
    quant_b_kernel<<<4, 256>>>(bK, pbk, 4);
    quant_b_kernel<<<4, 256>>>(bV, pbv, 5);

    // 3) input split fp32 -> bf16 hi/lo
    int n4 = (MR * DD) / 4;
    split_kernel<<<(n4 + 255) / 256, 256>>>((const float4*)Xq, (__nv_bfloat162*)pXqh, (__nv_bfloat162*)pXql, n4);
    split_kernel<<<(n4 + 255) / 256, 256>>>((const float4*)Xk, (__nv_bfloat162*)pXkh, (__nv_bfloat162*)pXkl, n4);
    split_kernel<<<(n4 + 255) / 256, 256>>>((const float4*)Xv, (__nv_bfloat162*)pXvh, (__nv_bfloat162*)pXvl, n4);

    // 4) rotary table
    sincos_kernel<<<SS * 32 / 256, 256>>>();

    // 5) projections on tensor cores (split-bf16, fp32 accumulate)
    dim3 gg(NC / 128, MR / 128);
    tgemm_kernel<<<gg, 256, GEMM_SMEM>>>(pXqh, pXql, pWqh, pWql, pbq, pq, MR, NC, DD);
    tgemm_kernel<<<gg, 256, GEMM_SMEM>>>(pXkh, pXkl, pWkh, pWkl, pbk, pk, MR, NC, DD);
    tgemm_kernel<<<gg, 256, GEMM_SMEM>>>(pXvh, pXvl, pWvh, pWvl, pbv, pv, MR, NC, DD);

    // 6) rotary (q gets 1/sqrt(Dh)=0.125 folded in)
    int rot_grid = (MR * HH * 32) / 256;
    rotary_kernel<<<rot_grid, 256>>>(pq, 0.125f);
    rotary_kernel<<<rot_grid, 256>>>(pk, 1.0f);

    // 7) causal flash attention (fp32)
    dim3 ag(SS / 64, HH, BB);
    attn_kernel<<<ag, 256, 4 * 64 * PADW * (int)sizeof(float)>>>(pq, pk, pv, pz);

    // 8) z split + output projection on tensor cores
    split_kernel<<<(n4 + 255) / 256, 256>>>((const float4*)pz, (__nv_bfloat162*)pzh, (__nv_bfloat162*)pzl, n4);
    tgemm_kernel<<<gg, 256, GEMM_SMEM>>>(pzh, pzl, pWoh, pWol, bO, out, MR, DD, NC);
}